// round 1
// baseline (speedup 1.0000x reference)
#include <cuda_runtime.h>
#include <cuda_bf16.h>
#include <stdint.h>

#define N 8192
#define NCHUNK 128            // N/64
#define IOU_THR 0.5f

// ---------------- device scratch (no allocations allowed) ----------------
__device__ float4 g_boxes[N];                 // decoded boxes, original order
__device__ float  g_ctr[N];                   // centerness, original order
__device__ int    g_maxbits;                  // boxes.max() as float bits (max is positive)
__device__ int    g_order[N];                 // sorted position -> original index
__device__ float4 g_sboxes[N];                // sorted, class-offset boxes
__device__ float  g_sarea[N];                 // areas of sorted offset boxes
__device__ unsigned long long g_mask[(size_t)N * NCHUNK];  // 8 MB suppression bitmask
__device__ unsigned char g_keep[N];           // keep flag, original order

// ---------------- K0: reset the max accumulator each replay ----------------
__global__ void init_kernel() {
    g_maxbits = 0;   // 0 == +0.0f; true max >= 36 so always positive -> signed-int atomicMax works
}

// ---------------- K1: decode boxes, centerness, global max ----------------
__global__ __launch_bounds__(256) void decode_kernel(const float* __restrict__ deltas,
                                                     const float* __restrict__ loc,
                                                     const float* __restrict__ gt,
                                                     const int*   __restrict__ stride_p) {
    int i = blockIdx.x * 256 + threadIdx.x;
    if (i >= N) return;
    float s  = (float)stride_p[0];
    float xc = loc[2 * i + 0];
    float yc = loc[2 * i + 1];
    float d0 = fmaxf(deltas[4 * i + 0], 0.0f);
    float d1 = fmaxf(deltas[4 * i + 1], 0.0f);
    float d2 = fmaxf(deltas[4 * i + 2], 0.0f);
    float d3 = fmaxf(deltas[4 * i + 3], 0.0f);
    float x1 = __fsub_rn(xc, __fmul_rn(d0, s));
    float y1 = __fsub_rn(yc, __fmul_rn(d1, s));
    float x2 = __fadd_rn(xc, __fmul_rn(d2, s));
    float y2 = __fadd_rn(yc, __fmul_rn(d3, s));
    g_boxes[i] = make_float4(x1, y1, x2, y2);

    // centerness from gt deltas
    float l = __fdiv_rn(__fsub_rn(xc, gt[4 * i + 0]), s);
    float t = __fdiv_rn(__fsub_rn(yc, gt[4 * i + 1]), s);
    float r = __fdiv_rn(__fsub_rn(gt[4 * i + 2], xc), s);
    float b = __fdiv_rn(__fsub_rn(gt[4 * i + 3], yc), s);
    float num = __fmul_rn(fminf(l, r), fminf(t, b));
    float den = __fmul_rn(fmaxf(l, r), fmaxf(t, b));
    g_ctr[i] = __fsqrt_rn(__fdiv_rn(num, den));

    // global max of all 4 coords (max is guaranteed positive -> int-bits atomicMax)
    float m = fmaxf(fmaxf(x1, y1), fmaxf(x2, y2));
    #pragma unroll
    for (int o = 16; o > 0; o >>= 1)
        m = fmaxf(m, __shfl_xor_sync(0xFFFFFFFFu, m, o));
    if ((threadIdx.x & 31) == 0)
        atomicMax(&g_maxbits, __float_as_int(m));
}

// ---------------- K2: stable sort by (-score, idx) ----------------
// key = (~score_bits << 32) | idx, ascending bitonic -> score desc, idx asc (stable tie-break).
__global__ __launch_bounds__(1024) void sort_kernel(const float* __restrict__ scores) {
    extern __shared__ unsigned long long sk[];
    int t = threadIdx.x;
    for (int p = t; p < N; p += 1024) {
        unsigned sb = __float_as_uint(scores[p]);           // scores >= 0 -> bits monotonic
        sk[p] = ((unsigned long long)(sb ^ 0xFFFFFFFFu) << 32) | (unsigned)p;
    }
    __syncthreads();
    for (int k = 2; k <= N; k <<= 1) {
        for (int j = k >> 1; j > 0; j >>= 1) {
            for (int p = t; p < N; p += 1024) {
                int q = p ^ j;
                if (q > p) {
                    bool up = ((p & k) == 0);
                    unsigned long long a = sk[p], b = sk[q];
                    if ((a > b) == up) { sk[p] = b; sk[q] = a; }
                }
            }
            __syncthreads();
        }
    }
    for (int p = t; p < N; p += 1024)
        g_order[p] = (int)(sk[p] & 0xFFFFFFFFu);
}

// ---------------- K3: gather sorted class-offset boxes + areas ----------------
__global__ __launch_bounds__(256) void gather_kernel(const int* __restrict__ class_ids) {
    int p = blockIdx.x * 256 + threadIdx.x;
    if (p >= N) return;
    int o = g_order[p];
    float maxv  = __int_as_float(g_maxbits);
    float scale = __fadd_rn(maxv, 1.0f);
    float off   = __fmul_rn((float)class_ids[o], scale);
    float4 b = g_boxes[o];
    float4 bn;
    bn.x = __fadd_rn(b.x, off);
    bn.y = __fadd_rn(b.y, off);
    bn.z = __fadd_rn(b.z, off);
    bn.w = __fadd_rn(b.w, off);
    g_sboxes[p] = bn;
    g_sarea[p]  = __fmul_rn(__fsub_rn(bn.z, bn.x), __fsub_rn(bn.w, bn.y));
}

// ---------------- K4: IoU suppression bitmask (upper triangle) ----------------
__global__ __launch_bounds__(64) void mask_kernel() {
    int rb = blockIdx.y;
    int cb = blockIdx.x;
    if (cb < rb) return;                 // only j > i region (+ diagonal)
    __shared__ float4 sb[64];
    __shared__ float  sa[64];
    int t = threadIdx.x;
    int j0 = cb * 64;
    sb[t] = g_sboxes[j0 + t];
    sa[t] = g_sarea[j0 + t];
    __syncthreads();
    int i = rb * 64 + t;
    float4 b  = g_sboxes[i];
    float  ai = g_sarea[i];
    unsigned long long bits = 0ull;
    #pragma unroll 8
    for (int k = 0; k < 64; ++k) {
        float4 o  = sb[k];
        float iw  = fmaxf(__fsub_rn(fminf(b.z, o.z), fmaxf(b.x, o.x)), 0.0f);
        float ih  = fmaxf(__fsub_rn(fminf(b.w, o.w), fmaxf(b.y, o.y)), 0.0f);
        float inter = __fmul_rn(iw, ih);
        float denom = __fsub_rn(__fadd_rn(ai, sa[k]), inter);
        float iou   = __fdiv_rn(inter, denom);        // exact IEEE div == XLA; NaN>thr is false
        bool sup = (iou > IOU_THR) && ((j0 + k) > i);
        bits |= ((unsigned long long)sup) << k;
    }
    g_mask[(size_t)i * NCHUNK + cb] = bits;
}

// ---------------- K5: sequential greedy NMS reduce (single block) ----------------
// 128 threads, one per 64-bit word of the "removed" bitmask. Per chunk c:
//   phase A: threads t>c prefetch all 64 candidate rows' word t (kept-independent addresses,
//            overlaps the serial resolve); threads <64 fetch diagonal words.
//   phase B: thread 0 serially resolves intra-chunk greedy suppression (ffs over kept bits).
//   phase C: branchless masked-OR of kept rows into removed[t].
__global__ __launch_bounds__(128, 1) void reduce_kernel() {
    __shared__ unsigned long long s_rem[NCHUNK];
    __shared__ unsigned long long s_diag[64];
    __shared__ unsigned long long s_kept;
    int t = threadIdx.x;
    s_rem[t] = 0ull;
    __syncthreads();

    for (int c = 0; c < NCHUNK; ++c) {
        unsigned long long v[64];
        const unsigned long long* base = g_mask + (size_t)(c * 64) * NCHUNK + t;
        if (t > c) {
            #pragma unroll
            for (int k = 0; k < 64; ++k)
                v[k] = base[(size_t)k * NCHUNK];
        }
        if (t < 64)
            s_diag[t] = g_mask[(size_t)(c * 64 + t) * NCHUNK + c];
        __syncthreads();

        if (t == 0) {
            unsigned long long rem  = s_rem[c];
            unsigned long long kept = 0ull;
            unsigned long long cand = ~rem;
            while (cand) {
                int k = __ffsll(cand) - 1;
                kept |= 1ull << k;
                rem  |= s_diag[k];              // diag has only bits > k
                cand &= ~(rem | (1ull << k));
            }
            s_rem[c] = rem;
            s_kept   = kept;
        }
        __syncthreads();

        if (t > c) {
            unsigned long long kk  = s_kept;
            unsigned long long acc = s_rem[t];
            #pragma unroll
            for (int k = 0; k < 64; ++k) {
                unsigned long long sel = 0ull - (unsigned long long)((kk >> k) & 1ull);
                acc |= v[k] & sel;
            }
            s_rem[t] = acc;
        }
        __syncthreads();
    }

    // scatter keep flags back to original order
    for (int p = t; p < N; p += 128) {
        int sup = (int)((s_rem[p >> 6] >> (p & 63)) & 1ull);
        g_keep[g_order[p]] = (unsigned char)(1 - sup);
    }
}

// ---------------- K6: assemble output ----------------
__global__ __launch_bounds__(256) void output_kernel(float* __restrict__ out) {
    int i = blockIdx.x * 256 + threadIdx.x;
    if (i >= N) return;
    float kf = (float)g_keep[i];
    float4 b = g_boxes[i];
    out[6 * i + 0] = __fmul_rn(b.x, kf);
    out[6 * i + 1] = __fmul_rn(b.y, kf);
    out[6 * i + 2] = __fmul_rn(b.z, kf);
    out[6 * i + 3] = __fmul_rn(b.w, kf);
    out[6 * i + 4] = g_ctr[i];
    out[6 * i + 5] = kf;
}

// ---------------- launch ----------------
extern "C" void kernel_launch(void* const* d_in, const int* in_sizes, int n_in,
                              void* d_out, int out_size) {
    const float* deltas = (const float*)d_in[0];
    const float* loc    = (const float*)d_in[1];
    const float* scores = (const float*)d_in[2];
    const int*   cls    = (const int*)  d_in[3];
    const float* gt     = (const float*)d_in[4];
    const int*   stride = (const int*)  d_in[5];
    float* out = (float*)d_out;

    cudaFuncSetAttribute(sort_kernel, cudaFuncAttributeMaxDynamicSharedMemorySize, N * 8);

    init_kernel<<<1, 1>>>();
    decode_kernel<<<N / 256, 256>>>(deltas, loc, gt, stride);
    sort_kernel<<<1, 1024, N * 8>>>(scores);
    gather_kernel<<<N / 256, 256>>>(cls);
    mask_kernel<<<dim3(NCHUNK, NCHUNK), 64>>>();
    reduce_kernel<<<1, 128>>>();
    output_kernel<<<N / 256, 256>>>(out);
}